// round 1
// baseline (speedup 1.0000x reference)
#include <cuda_runtime.h>
#include <math.h>

#define NB 8
#define C 256
#define C2 128
#define P 4096          // 64*64 pixels
#define COUT3 768

// ---------------- scratch (device globals; no allocs allowed) ----------------
__device__ float g_pos[C * P];                 // positional encoding, 4 MB
__device__ float g_expx[NB * COUT3 * P];       // expansion conv output, 100 MB
__device__ float g_cat[NB * COUT3 * P];        // f_i + expx (concat), 100 MB
__device__ float g_out[NB * C * P];            // res conv output, 33.5 MB
__device__ float g_T[3][NB * P];               // ch_wq logits per branch
__device__ float g_xs[3][NB * C];              // sum_p cnt*X
__device__ float g_ys[3][NB * C];              // sum_p cnt*e^T*X
__device__ float g_Z[3][NB];                   // sum_p cnt*e^T
__device__ float g_chw[3][NB * C];             // channel gate
__device__ float g_v[3][NB * C];               // spatial-gate projection vector
__device__ float g_beta[3][NB];                // spatial-gate bias

// coverage count for win=6 (kh=14, sh=10, 6 patches)
__device__ __forceinline__ int cov6(int h) {
    int r = 0;
#pragma unroll
    for (int j = 0; j < 6; j++) r += (h >= 10 * j) && (h <= 10 * j + 13);
    return r;
}

__device__ __forceinline__ float sigmoidf_(float x) {
    return 1.0f / (1.0f + expf(-x));
}

// ---------------- K1: positional encoding ----------------
// pe (4096 rows x 256 cols) row-major, reinterpreted as [c][h][w] flat.
// row prow = i*64 + j (i = W coord, j = H coord); omega[k] = 10000^(-k/64).
__global__ void pos_kernel() {
    int idx = blockIdx.x * blockDim.x + threadIdx.x;  // < C*P
    int prow = idx >> 8;
    int c = idx & 255;
    int i = prow >> 6;
    int j = prow & 63;
    int k = c & 63;
    float omega = powf(10000.0f, -(float)k / 64.0f);
    float coord = (c < 128) ? (float)i : (float)j;
    float a = coord * omega;
    float val = ((c >> 6) & 1) ? cosf(a) : sinf(a);
    g_pos[idx] = val;
}

// ---------------- generic SGEMM: Y[n,o,p] = sum_c W[o,c]*X[n,c,p] + bias[o] (+ add) ----
__global__ __launch_bounds__(256) void sgemm_kernel(
    const float* __restrict__ W, const float* __restrict__ X,
    const float* __restrict__ bias, const float* __restrict__ add,
    float* __restrict__ Y, int Cin, int Cout)
{
    __shared__ float Ws[16][64];
    __shared__ float Xs[16][64];
    int n = blockIdx.z;
    const float* Xn = X + (size_t)n * Cin * P;
    float* Yn = Y + (size_t)n * Cout * P;
    int row0 = blockIdx.y * 64, col0 = blockIdx.x * 64;
    int tid = threadIdx.x, tx = tid & 15, ty = tid >> 4;
    float acc[4][4] = {};

    for (int k0 = 0; k0 < Cin; k0 += 16) {
#pragma unroll
        for (int it = 0; it < 4; it++) {
            int idx = it * 256 + tid;
            int m = idx >> 4, k = idx & 15;
            Ws[k][m] = W[(size_t)(row0 + m) * Cin + k0 + k];
        }
#pragma unroll
        for (int it = 0; it < 4; it++) {
            int idx = it * 256 + tid;
            int k = idx >> 6, p = idx & 63;
            Xs[k][p] = Xn[(size_t)(k0 + k) * P + col0 + p];
        }
        __syncthreads();
#pragma unroll
        for (int k = 0; k < 16; k++) {
            float4 a4 = *(const float4*)&Ws[k][ty * 4];
            float4 b4 = *(const float4*)&Xs[k][tx * 4];
            float av[4] = {a4.x, a4.y, a4.z, a4.w};
            float bv[4] = {b4.x, b4.y, b4.z, b4.w};
#pragma unroll
            for (int i = 0; i < 4; i++)
#pragma unroll
                for (int j = 0; j < 4; j++) acc[i][j] += av[i] * bv[j];
        }
        __syncthreads();
    }

#pragma unroll
    for (int i = 0; i < 4; i++) {
        int o = row0 + ty * 4 + i;
        float bo = bias[o];
#pragma unroll
        for (int j = 0; j < 4; j++) {
            int p = col0 + tx * 4 + j;
            float r = acc[i][j] + bo;
            if (add) r += add[((size_t)n * Cout + o) * P + p];
            Yn[(size_t)o * P + p] = r;
        }
    }
}

// ---------------- K3: per-pixel ch_wq logits T ----------------
__global__ __launch_bounds__(128) void tq_kernel(const float* __restrict__ wq,
                                                 const float* __restrict__ bq) {
    int b = blockIdx.z, n = blockIdx.y;
    int p = blockIdx.x * 128 + threadIdx.x;
    __shared__ float wqs[C];
    for (int c = threadIdx.x; c < C; c += 128) wqs[c] = wq[c];
    __syncthreads();
    const float* E = g_expx + ((size_t)n * COUT3 + b * C) * P;
    float acc = 0.f;
#pragma unroll 8
    for (int c = 0; c < C; c++)
        acc += wqs[c] * (E[(size_t)c * P + p] + g_pos[(size_t)c * P + p]);
    g_T[b][n * P + p] = acc + bq[0];
}

// ---------------- K4: per-(branch,n,c) reductions over pixels ----------------
__global__ __launch_bounds__(256) void red_kernel() {
    int b = blockIdx.z, n = blockIdx.y, c = blockIdx.x;
    const float* E = g_expx + ((size_t)n * COUT3 + b * C + c) * P;
    const float* Pp = g_pos + (size_t)c * P;
    const float* Tn = &g_T[b][n * P];
    float xs = 0.f, ys = 0.f, zs = 0.f;
    for (int t = threadIdx.x; t < P; t += 256) {
        float w = 1.f;
        if (b == 2) {
            int h = t >> 6, wc = t & 63;
            w = (float)(cov6(h) * cov6(wc));
        }
        float X = E[t] + Pp[t];
        float e = expf(Tn[t]);
        xs += w * X;
        ys += w * e * X;
        zs += w * e;
    }
    __shared__ float red[256];
    int t = threadIdx.x;
    red[t] = xs; __syncthreads();
    for (int s = 128; s > 0; s >>= 1) { if (t < s) red[t] += red[t + s]; __syncthreads(); }
    if (t == 0) g_xs[b][n * C + c] = red[0];
    __syncthreads();
    red[t] = ys; __syncthreads();
    for (int s = 128; s > 0; s >>= 1) { if (t < s) red[t] += red[t + s]; __syncthreads(); }
    if (t == 0) g_ys[b][n * C + c] = red[0];
    __syncthreads();
    red[t] = zs; __syncthreads();
    for (int s = 128; s > 0; s >>= 1) { if (t < s) red[t] += red[t + s]; __syncthreads(); }
    if (t == 0 && c == 0) g_Z[b][n] = red[0];
}

// ---------------- K5: tiny per-(n,branch) GEMV chains ----------------
__global__ __launch_bounds__(256) void tiny_kernel(
    const float* __restrict__ Wv, const float* __restrict__ bv,
    const float* __restrict__ Wz, const float* __restrict__ bz,
    const float* __restrict__ lg, const float* __restrict__ lb,
    const float* __restrict__ Wqs, const float* __restrict__ bqs,
    const float* __restrict__ Wvs, const float* __restrict__ bvs)
{
    int n = blockIdx.x, b = blockIdx.y;
    __shared__ float y[C], xb[C], zz[C2], sq[C2], wzs[C], red[256];
    int t = threadIdx.x;
    float L = (b == 2) ? 7056.f : 4096.f;
    float Zn = g_Z[b][n];
    y[t] = g_ys[b][n * C + t] / Zn;
    xb[t] = g_xs[b][n * C + t] / L;
    __syncthreads();

    // z = Wv @ y + bv   (128 x 256)
    if (t < C2) {
        float a = 0.f;
        for (int c = 0; c < C; c++) a += Wv[t * C + c] * y[c];
        zz[t] = a + bv[t];
    }
    __syncthreads();

    // wz = Wz @ z + bz  (256 x 128)
    {
        float a = 0.f;
        for (int c2 = 0; c2 < C2; c2++) a += Wz[t * C2 + c2] * zz[c2];
        wzs[t] = a + bz[t];
    }
    __syncthreads();

    // layernorm over 256, sigmoid gate
    red[t] = wzs[t]; __syncthreads();
    for (int s = 128; s > 0; s >>= 1) { if (t < s) red[t] += red[t + s]; __syncthreads(); }
    float m = red[0] / 256.f; __syncthreads();
    float d = wzs[t] - m;
    red[t] = d * d; __syncthreads();
    for (int s = 128; s > 0; s >>= 1) { if (t < s) red[t] += red[t + s]; __syncthreads(); }
    float var = red[0] / 256.f; __syncthreads();
    g_chw[b][n * C + t] = sigmoidf_(d * rsqrtf(var + 1e-5f) * lg[t] + lb[t]);

    // g = Wqs @ xbar + bqs  -> softmax over 128 -> sq
    if (t < C2) {
        float a = 0.f;
        for (int c = 0; c < C; c++) a += Wqs[t * C + c] * xb[c];
        zz[t] = a + bqs[t];
    }
    __syncthreads();
    red[t] = (t < C2) ? zz[t] : -1e30f; __syncthreads();
    for (int s = 128; s > 0; s >>= 1) { if (t < s) red[t] = fmaxf(red[t], red[t + s]); __syncthreads(); }
    float mx = red[0]; __syncthreads();
    float e = (t < C2) ? expf(zz[t] - mx) : 0.f;
    if (t < C2) sq[t] = e;
    red[t] = e; __syncthreads();
    for (int s = 128; s > 0; s >>= 1) { if (t < s) red[t] += red[t + s]; __syncthreads(); }
    float se = red[0]; __syncthreads();
    if (t < C2) sq[t] /= se;
    __syncthreads();

    // v[c] = sum_c2 sq[c2]*Wvs[c2,c];  beta = sq . bvs
    {
        float a = 0.f;
        for (int c2 = 0; c2 < C2; c2++) a += sq[c2] * Wvs[c2 * C + t];
        g_v[b][n * C + t] = a;
    }
    red[t] = (t < C2) ? sq[t] * bvs[t] : 0.f; __syncthreads();
    for (int s = 128; s > 0; s >>= 1) { if (t < s) red[t] += red[t + s]; __syncthreads(); }
    if (t == 0) g_beta[b][n] = red[0];
}

// ---------------- K6: spatial gate S + write f_i + expx into cat ----------------
__global__ __launch_bounds__(128) void sf_kernel() {
    int b = blockIdx.z, n = blockIdx.y;
    int p = blockIdx.x * 128 + threadIdx.x;
    __shared__ float vs[C], cs[C];
    for (int c = threadIdx.x; c < C; c += 128) {
        vs[c] = g_v[b][n * C + c];
        cs[c] = g_chw[b][n * C + c];
    }
    __syncthreads();
    const float* E = g_expx + ((size_t)n * COUT3 + b * C) * P;
    float acc = 0.f;
#pragma unroll 8
    for (int c = 0; c < C; c++)
        acc += vs[c] * (E[(size_t)c * P + p] + g_pos[(size_t)c * P + p]);
    float S = sigmoidf_(acc + g_beta[b][n]);
    float* O = g_cat + ((size_t)n * COUT3 + b * C) * P;
#pragma unroll 4
    for (int c = 0; c < C; c++) {
        float e = E[(size_t)c * P + p];
        float X = e + g_pos[(size_t)c * P + p];
        O[(size_t)c * P + p] = X * (cs[c] + S) + e;
    }
}

// ---------------- host ----------------
extern "C" void kernel_launch(void* const* d_in, const int* in_sizes, int n_in,
                              void* d_out, int out_size) {
    const float* x       = (const float*)d_in[0];
    const float* w_exp   = (const float*)d_in[1];
    const float* b_exp   = (const float*)d_in[2];
    const float* w_res   = (const float*)d_in[3];
    const float* b_res   = (const float*)d_in[4];
    const float* w_fus   = (const float*)d_in[5];
    const float* b_fus   = (const float*)d_in[6];
    const float* ch_wv_w = (const float*)d_in[7];
    const float* ch_wv_b = (const float*)d_in[8];
    const float* ch_wq_w = (const float*)d_in[9];
    const float* ch_wq_b = (const float*)d_in[10];
    const float* ch_wz_w = (const float*)d_in[11];
    const float* ch_wz_b = (const float*)d_in[12];
    const float* ln_g    = (const float*)d_in[13];
    const float* ln_b    = (const float*)d_in[14];
    const float* sp_wv_w = (const float*)d_in[15];
    const float* sp_wv_b = (const float*)d_in[16];
    const float* sp_wq_w = (const float*)d_in[17];
    const float* sp_wq_b = (const float*)d_in[18];

    float *p_expx, *p_cat, *p_out;
    cudaGetSymbolAddress((void**)&p_expx, g_expx);
    cudaGetSymbolAddress((void**)&p_cat, g_cat);
    cudaGetSymbolAddress((void**)&p_out, g_out);

    pos_kernel<<<(C * P) / 256, 256>>>();
    sgemm_kernel<<<dim3(P / 64, COUT3 / 64, NB), 256>>>(w_exp, x, b_exp, nullptr,
                                                        p_expx, C, COUT3);
    tq_kernel<<<dim3(P / 128, NB, 3), 128>>>(ch_wq_w, ch_wq_b);
    red_kernel<<<dim3(C, NB, 3), 256>>>();
    tiny_kernel<<<dim3(NB, 3), 256>>>(ch_wv_w, ch_wv_b, ch_wz_w, ch_wz_b,
                                      ln_g, ln_b, sp_wq_w, sp_wq_b,
                                      sp_wv_w, sp_wv_b);
    sf_kernel<<<dim3(P / 128, NB, 3), 128>>>();
    sgemm_kernel<<<dim3(P / 64, C / 64, NB), 256>>>(w_res, p_cat, b_res, x,
                                                    p_out, COUT3, C);
    sgemm_kernel<<<dim3(P / 64, C / 64, NB), 256>>>(w_fus, p_out, b_fus, nullptr,
                                                    (float*)d_out, C, C);
}